// round 13
// baseline (speedup 1.0000x reference)
#include <cuda_runtime.h>
#include <math.h>
typedef unsigned long long ull;

#define TSTEPS 512
#define HDIM 1024

#define FFMA2(acc,a,b) asm("fma.rn.f32x2 %0, %1, %2, %0;" : "+l"(acc) : "l"(a), "l"(b))
__device__ __forceinline__ float psum(ull v){
    float x, y;
    asm("mov.b64 {%0,%1}, %2;" : "=f"(x), "=f"(y) : "l"(v));
    return x + y;
}

// per-CTA progress flags: flag[rg*32+cg] = number of completed steps
__device__ int g_flag[128];
__global__ void reset_kernel(){
    int i = blockIdx.x * blockDim.x + threadIdx.x;
    if (i < 128) g_flag[i] = 0;
}

// ---------------------------------------------------------------------------
// Phase 1 (unchanged, proven ~2.8ms): C = A @ W + b, 128x128, FFMA2 K-paired.
// ---------------------------------------------------------------------------
#define SA 20
__global__ void __launch_bounds__(256, 1) gemm_xw(
    const float* __restrict__ A, const float* __restrict__ W,
    const float* __restrict__ bias, float* __restrict__ C)
{
    __shared__ float sA[2][128 * SA];
    __shared__ float sB[2][8 * 256];
    const int tid = threadIdx.x;
    const int n0 = blockIdx.x * 128, m0 = blockIdx.y * 128;
    const int ty = tid >> 4, tx = tid & 15;
    const int ar = tid >> 1, ah = (tid & 1) * 8;
    const int wn = tid & 127, wk0 = tid >> 7;

    ull acc[8][8];
    #pragma unroll
    for (int i = 0; i < 8; i++)
        #pragma unroll
        for (int j = 0; j < 8; j++) acc[i][j] = 0ull;

    const float* Ap = A + (size_t)(m0 + ar) * HDIM + ah;
    float4 pa0, pa1; float pw[8];
    pa0 = *(const float4*)Ap;
    pa1 = *(const float4*)(Ap + 4);
    #pragma unroll
    for (int q = 0; q < 4; q++) {
        int kp = wk0 + q * 2;
        pw[q*2+0] = W[(size_t)(2*kp+0) * HDIM + n0 + wn];
        pw[q*2+1] = W[(size_t)(2*kp+1) * HDIM + n0 + wn];
    }
    int buf = 0;
    *(float4*)&sA[0][ar*SA + ah] = pa0;
    *(float4*)&sA[0][ar*SA + ah + 4] = pa1;
    #pragma unroll
    for (int q = 0; q < 4; q++) {
        int kp = wk0 + q * 2;
        sB[0][kp*256 + 2*wn]     = pw[q*2+0];
        sB[0][kp*256 + 2*wn + 1] = pw[q*2+1];
    }
    __syncthreads();

    for (int kt = 0; kt < HDIM / 16; kt++) {
        if (kt < HDIM/16 - 1) {
            const float* An = Ap + (kt + 1) * 16;
            pa0 = *(const float4*)An;
            pa1 = *(const float4*)(An + 4);
            #pragma unroll
            for (int q = 0; q < 4; q++) {
                int kp = wk0 + q * 2;
                int k = (kt + 1) * 16 + 2 * kp;
                pw[q*2+0] = W[(size_t)k * HDIM + n0 + wn];
                pw[q*2+1] = W[(size_t)(k+1) * HDIM + n0 + wn];
            }
        }
        const float* cA = sA[buf];
        const float* cB = sB[buf];
        #pragma unroll
        for (int kq = 0; kq < 4; kq++) {
            ull a0[8], a1[8], w0[8], w1[8];
            #pragma unroll
            for (int i = 0; i < 8; i++) {
                ulonglong2 v = *(const ulonglong2*)&cA[(ty + 16*i) * SA + kq*4];
                a0[i] = v.x; a1[i] = v.y;
            }
            #pragma unroll
            for (int j = 0; j < 8; j++) {
                w0[j] = *(const ull*)&cB[(kq*2+0)*256 + 2*(tx + 16*j)];
                w1[j] = *(const ull*)&cB[(kq*2+1)*256 + 2*(tx + 16*j)];
            }
            #pragma unroll
            for (int i = 0; i < 8; i++)
                #pragma unroll
                for (int j = 0; j < 8; j++) {
                    FFMA2(acc[i][j], a0[i], w0[j]);
                    FFMA2(acc[i][j], a1[i], w1[j]);
                }
        }
        if (kt < HDIM/16 - 1) {
            int nb = buf ^ 1;
            *(float4*)&sA[nb][ar*SA + ah] = pa0;
            *(float4*)&sA[nb][ar*SA + ah + 4] = pa1;
            #pragma unroll
            for (int q = 0; q < 4; q++) {
                int kp = wk0 + q * 2;
                sB[nb][kp*256 + 2*wn]     = pw[q*2+0];
                sB[nb][kp*256 + 2*wn + 1] = pw[q*2+1];
            }
        }
        __syncthreads();
        buf ^= 1;
    }
    #pragma unroll
    for (int j = 0; j < 8; j++) {
        float bb = bias[n0 + tx + 16*j];
        #pragma unroll
        for (int i = 0; i < 8; i++)
            C[(size_t)(m0 + ty + 16*i) * HDIM + n0 + tx + 16*j] = psum(acc[i][j]) + bb;
    }
}

// ---------------------------------------------------------------------------
// Phase 2: persistent scan — R1 compute structure VERBATIM (proven fastest),
// with the per-step global barrier replaced by per-CTA progress flags:
// chunk kc of step t waits only on its 8 producer CTAs (cols 256kc..+255),
// absorbing inter-SM skew instead of convoying every step.
// ---------------------------------------------------------------------------
#define WH_STRIDE 36
#define SH_STRIDE 34
#define SCAN_SMEM ((HDIM * WH_STRIDE + 256 * SH_STRIDE) * 4)

__global__ void __launch_bounds__(256) scan_kernel(
    const float* __restrict__ h0, const float* __restrict__ Wh,
    float* __restrict__ out)
{
    extern __shared__ float smem[];
    float* sWh = smem;                    // [1024][WH_STRIDE]
    float* sh  = smem + HDIM * WH_STRIDE; // [256][SH_STRIDE]

    const int tid = threadIdx.x;
    const int cg = blockIdx.x;   // 0..31 column group
    const int rg = blockIdx.y;   // 0..3  row group
    const int ty = tid >> 4;     // rows 2ty..+1
    const int tx = tid & 15;     // cols 2tx..+1

    // load Wh slice once: cols [cg*32, cg*32+32)
    {
        const int kb = tid >> 3;
        const int j4 = (tid & 7) * 4;
        #pragma unroll 4
        for (int it = 0; it < 32; ++it) {
            int k = kb + it * 32;
            float4 w = *(const float4*)&Wh[(size_t)k * HDIM + cg * 32 + j4];
            *(float4*)&sWh[k * WH_STRIDE + j4] = w;
        }
    }
    __syncthreads();

    const int r = tid >> 3;
    const int x = tid & 7;
    const int row = rg * 32 + r;

    volatile int* flags = g_flag + rg * 32;
    int* myflag = g_flag + rg * 32 + cg;

    for (int t = 0; t < TSTEPS; ++t) {
        float acc00 = 0.f, acc01 = 0.f, acc10 = 0.f, acc11 = 0.f;
        const float* hrow = (t == 0)
            ? (h0 + (size_t)row * HDIM)
            : (out + ((size_t)row * TSTEPS + (t - 1)) * HDIM);

        #pragma unroll 1
        for (int kc = 0; kc < 4; ++kc) {
            // wait for the 8 producer CTAs of cols [256kc, 256kc+256)
            if (t > 0) {
                if (tid == 0) {
                    const volatile int* f = flags + kc * 8;
                    for (;;) {
                        int m = f[0]; m = min(m, f[1]); m = min(m, f[2]);
                        m = min(m, f[3]); m = min(m, f[4]); m = min(m, f[5]);
                        m = min(m, f[6]); m = min(m, f[7]);
                        if (m >= t) break;
                    }
                    __threadfence();
                }
                __syncthreads();
            }
            // stage h chunk transposed: sh[lk][r]
            #pragma unroll
            for (int q = 0; q < 8; ++q) {
                int lk = x * 4 + q * 32;
                float4 v = *(const float4*)&hrow[kc * 256 + lk];
                sh[(lk + 0) * SH_STRIDE + r] = v.x;
                sh[(lk + 1) * SH_STRIDE + r] = v.y;
                sh[(lk + 2) * SH_STRIDE + r] = v.z;
                sh[(lk + 3) * SH_STRIDE + r] = v.w;
            }
            __syncthreads();

            const float* hbase = sh + ty * 2;
            const float* wbase = sWh + (size_t)(kc * 256) * WH_STRIDE + tx * 2;
            #pragma unroll 8
            for (int lk = 0; lk < 256; ++lk) {
                float2 a = *(const float2*)(hbase + lk * SH_STRIDE);
                float2 w = *(const float2*)(wbase + lk * WH_STRIDE);
                acc00 += a.x * w.x;
                acc01 += a.x * w.y;
                acc10 += a.y * w.x;
                acc11 += a.y * w.y;
            }
            __syncthreads();
        }

        // epilogue: h = tanh(acc + xw) written in place over xw
        {
            int m0 = rg * 32 + ty * 2;
            int n  = cg * 32 + tx * 2;
            float* p0 = out + ((size_t)m0 * TSTEPS + t) * HDIM + n;
            float* p1 = out + ((size_t)(m0 + 1) * TSTEPS + t) * HDIM + n;
            float2 xw0 = *(const float2*)p0;
            float2 xw1 = *(const float2*)p1;
            float2 o0, o1;
            o0.x = tanhf(acc00 + xw0.x);
            o0.y = tanhf(acc01 + xw0.y);
            o1.x = tanhf(acc10 + xw1.x);
            o1.y = tanhf(acc11 + xw1.y);
            *(float2*)p0 = o0;
            *(float2*)p1 = o1;
        }

        // publish progress: this CTA finished step t
        if (t < TSTEPS - 1) {
            __threadfence();
            __syncthreads();
            if (tid == 0) *(volatile int*)myflag = t + 1;
        }
    }
}

extern "C" void kernel_launch(void* const* d_in, const int* in_sizes, int n_in,
                              void* d_out, int out_size) {
    const float* x  = (const float*)d_in[0];
    const float* h0 = (const float*)d_in[1];
    const float* Wx = (const float*)d_in[2];
    const float* Wh = (const float*)d_in[3];
    const float* b  = (const float*)d_in[4];
    float* out = (float*)d_out;

    {
        dim3 grid(HDIM / 128, 65536 / 128);
        gemm_xw<<<grid, 256>>>(x, Wx, b, out);
    }
    reset_kernel<<<1, 128>>>();
    {
        static int done = 0;
        if (!done) {
            cudaFuncSetAttribute(scan_kernel,
                cudaFuncAttributeMaxDynamicSharedMemorySize, SCAN_SMEM);
            done = 1;
        }
        dim3 grid(32, 4);
        scan_kernel<<<grid, 256, SCAN_SMEM>>>(h0, Wh, out);
    }
}

// round 14
// speedup vs baseline: 1.4771x; 1.4771x over previous
#include <cuda_runtime.h>
#include <math.h>
typedef unsigned long long ull;

#define TSTEPS 512
#define HDIM 1024

#define FFMA2(acc,a,b) asm("fma.rn.f32x2 %0, %1, %2, %0;" : "+l"(acc) : "l"(a), "l"(b))
__device__ __forceinline__ float psum(ull v){
    float x, y;
    asm("mov.b64 {%0,%1}, %2;" : "=f"(x), "=f"(y) : "l"(v));
    return x + y;
}

// per-rowgroup, per-step arrival counters (4 rowgroups x 512 steps)
__device__ int g_cnt[4 * TSTEPS];
__global__ void reset_kernel(){
    int i = blockIdx.x * blockDim.x + threadIdx.x;
    if (i < 4 * TSTEPS) g_cnt[i] = 0;
}

// ---------------------------------------------------------------------------
// Phase 1 (R7, verified 2.80ms): C = A @ W + b, 128x128 tile, 256 threads,
// 8x8/thread, BK=16, double-buffered, K-paired FFMA2 accumulators.
// ---------------------------------------------------------------------------
#define SA 20
__global__ void __launch_bounds__(256, 1) gemm_xw(
    const float* __restrict__ A, const float* __restrict__ W,
    const float* __restrict__ bias, float* __restrict__ C)
{
    __shared__ float sA[2][128 * SA];
    __shared__ float sB[2][8 * 256];
    const int tid = threadIdx.x;
    const int n0 = blockIdx.x * 128, m0 = blockIdx.y * 128;
    const int ty = tid >> 4, tx = tid & 15;
    const int ar = tid >> 1, ah = (tid & 1) * 8;
    const int wn = tid & 127, wk0 = tid >> 7;

    ull acc[8][8];
    #pragma unroll
    for (int i = 0; i < 8; i++)
        #pragma unroll
        for (int j = 0; j < 8; j++) acc[i][j] = 0ull;

    const float* Ap = A + (size_t)(m0 + ar) * HDIM + ah;
    float4 pa0, pa1; float pw[8];
    pa0 = *(const float4*)Ap;
    pa1 = *(const float4*)(Ap + 4);
    #pragma unroll
    for (int q = 0; q < 4; q++) {
        int kp = wk0 + q * 2;
        pw[q*2+0] = W[(size_t)(2*kp+0) * HDIM + n0 + wn];
        pw[q*2+1] = W[(size_t)(2*kp+1) * HDIM + n0 + wn];
    }
    int buf = 0;
    *(float4*)&sA[0][ar*SA + ah] = pa0;
    *(float4*)&sA[0][ar*SA + ah + 4] = pa1;
    #pragma unroll
    for (int q = 0; q < 4; q++) {
        int kp = wk0 + q * 2;
        sB[0][kp*256 + 2*wn]     = pw[q*2+0];
        sB[0][kp*256 + 2*wn + 1] = pw[q*2+1];
    }
    __syncthreads();

    for (int kt = 0; kt < HDIM / 16; kt++) {
        if (kt < HDIM/16 - 1) {
            const float* An = Ap + (kt + 1) * 16;
            pa0 = *(const float4*)An;
            pa1 = *(const float4*)(An + 4);
            #pragma unroll
            for (int q = 0; q < 4; q++) {
                int kp = wk0 + q * 2;
                int k = (kt + 1) * 16 + 2 * kp;
                pw[q*2+0] = W[(size_t)k * HDIM + n0 + wn];
                pw[q*2+1] = W[(size_t)(k+1) * HDIM + n0 + wn];
            }
        }
        const float* cA = sA[buf];
        const float* cB = sB[buf];
        #pragma unroll
        for (int kq = 0; kq < 4; kq++) {
            ull a0[8], a1[8], w0[8], w1[8];
            #pragma unroll
            for (int i = 0; i < 8; i++) {
                ulonglong2 v = *(const ulonglong2*)&cA[(ty + 16*i) * SA + kq*4];
                a0[i] = v.x; a1[i] = v.y;
            }
            #pragma unroll
            for (int j = 0; j < 8; j++) {
                w0[j] = *(const ull*)&cB[(kq*2+0)*256 + 2*(tx + 16*j)];
                w1[j] = *(const ull*)&cB[(kq*2+1)*256 + 2*(tx + 16*j)];
            }
            #pragma unroll
            for (int i = 0; i < 8; i++)
                #pragma unroll
                for (int j = 0; j < 8; j++) {
                    FFMA2(acc[i][j], a0[i], w0[j]);
                    FFMA2(acc[i][j], a1[i], w1[j]);
                }
        }
        if (kt < HDIM/16 - 1) {
            int nb = buf ^ 1;
            *(float4*)&sA[nb][ar*SA + ah] = pa0;
            *(float4*)&sA[nb][ar*SA + ah + 4] = pa1;
            #pragma unroll
            for (int q = 0; q < 4; q++) {
                int kp = wk0 + q * 2;
                sB[nb][kp*256 + 2*wn]     = pw[q*2+0];
                sB[nb][kp*256 + 2*wn + 1] = pw[q*2+1];
            }
        }
        __syncthreads();
        buf ^= 1;
    }
    #pragma unroll
    for (int j = 0; j < 8; j++) {
        float bb = bias[n0 + tx + 16*j];
        #pragma unroll
        for (int i = 0; i < 8; i++)
            C[(size_t)(m0 + ty + 16*i) * HDIM + n0 + tx + 16*j] = psum(acc[i][j]) + bb;
    }
}

// ---------------------------------------------------------------------------
// Phase 2 (R1 scan, verified 8.85ms): persistent, 128 CTAs (32 cg x 4 rg),
// 256 threads, 2x2 tile, Wh slice resident, counter barrier per step.
// ---------------------------------------------------------------------------
#define WH_STRIDE 36
#define SH_STRIDE 34
#define SCAN_SMEM ((HDIM * WH_STRIDE + 256 * SH_STRIDE) * 4)

__global__ void __launch_bounds__(256) scan_kernel(
    const float* __restrict__ h0, const float* __restrict__ Wh,
    float* __restrict__ out)
{
    extern __shared__ float smem[];
    float* sWh = smem;                    // [1024][WH_STRIDE]
    float* sh  = smem + HDIM * WH_STRIDE; // [256][SH_STRIDE]

    const int tid = threadIdx.x;
    const int cg = blockIdx.x;   // 0..31 column group
    const int rg = blockIdx.y;   // 0..3  row group
    const int ty = tid >> 4;     // rows 2ty..+1
    const int tx = tid & 15;     // cols 2tx..+1

    // load Wh slice once: cols [cg*32, cg*32+32)
    {
        const int kb = tid >> 3;
        const int j4 = (tid & 7) * 4;
        #pragma unroll 4
        for (int it = 0; it < 32; ++it) {
            int k = kb + it * 32;
            float4 w = *(const float4*)&Wh[(size_t)k * HDIM + cg * 32 + j4];
            *(float4*)&sWh[k * WH_STRIDE + j4] = w;
        }
    }
    __syncthreads();

    const int r = tid >> 3;
    const int x = tid & 7;
    const int row = rg * 32 + r;

    int* cnt = &g_cnt[rg * TSTEPS];

    for (int t = 0; t < TSTEPS; ++t) {
        float acc00 = 0.f, acc01 = 0.f, acc10 = 0.f, acc11 = 0.f;
        const float* hrow = (t == 0)
            ? (h0 + (size_t)row * HDIM)
            : (out + ((size_t)row * TSTEPS + (t - 1)) * HDIM);

        #pragma unroll 1
        for (int kc = 0; kc < 4; ++kc) {
            // stage h chunk transposed: sh[lk][r]
            #pragma unroll
            for (int q = 0; q < 8; ++q) {
                int lk = x * 4 + q * 32;
                float4 v = *(const float4*)&hrow[kc * 256 + lk];
                sh[(lk + 0) * SH_STRIDE + r] = v.x;
                sh[(lk + 1) * SH_STRIDE + r] = v.y;
                sh[(lk + 2) * SH_STRIDE + r] = v.z;
                sh[(lk + 3) * SH_STRIDE + r] = v.w;
            }
            __syncthreads();

            const float* hbase = sh + ty * 2;
            const float* wbase = sWh + (size_t)(kc * 256) * WH_STRIDE + tx * 2;
            #pragma unroll 8
            for (int lk = 0; lk < 256; ++lk) {
                float2 a = *(const float2*)(hbase + lk * SH_STRIDE);
                float2 w = *(const float2*)(wbase + lk * WH_STRIDE);
                acc00 += a.x * w.x;
                acc01 += a.x * w.y;
                acc10 += a.y * w.x;
                acc11 += a.y * w.y;
            }
            __syncthreads();
        }

        // epilogue: h = tanh(acc + xw) written in place over xw
        {
            int m0 = rg * 32 + ty * 2;
            int n  = cg * 32 + tx * 2;
            float* p0 = out + ((size_t)m0 * TSTEPS + t) * HDIM + n;
            float* p1 = out + ((size_t)(m0 + 1) * TSTEPS + t) * HDIM + n;
            float2 xw0 = *(const float2*)p0;
            float2 xw1 = *(const float2*)p1;
            float2 o0, o1;
            o0.x = tanhf(acc00 + xw0.x);
            o0.y = tanhf(acc01 + xw0.y);
            o1.x = tanhf(acc10 + xw1.x);
            o1.y = tanhf(acc11 + xw1.y);
            *(float2*)p0 = o0;
            *(float2*)p1 = o1;
        }

        // inter-step barrier among the 32 CTAs of this rowgroup
        if (t < TSTEPS - 1) {
            __threadfence();
            __syncthreads();
            if (tid == 0) {
                atomicAdd(cnt + t, 1);
                while (((volatile int*)cnt)[t] < 32) { }
                __threadfence();
            }
            __syncthreads();
        }
    }
}

extern "C" void kernel_launch(void* const* d_in, const int* in_sizes, int n_in,
                              void* d_out, int out_size) {
    const float* x  = (const float*)d_in[0];
    const float* h0 = (const float*)d_in[1];
    const float* Wx = (const float*)d_in[2];
    const float* Wh = (const float*)d_in[3];
    const float* b  = (const float*)d_in[4];
    float* out = (float*)d_out;

    {
        dim3 grid(HDIM / 128, 65536 / 128);
        gemm_xw<<<grid, 256>>>(x, Wx, b, out);
    }
    reset_kernel<<<4, 512>>>();
    {
        static int done = 0;
        if (!done) {
            cudaFuncSetAttribute(scan_kernel,
                cudaFuncAttributeMaxDynamicSharedMemorySize, SCAN_SMEM);
            done = 1;
        }
        dim3 grid(32, 4);
        scan_kernel<<<grid, 256, SCAN_SMEM>>>(h0, Wh, out);
    }
}